// round 17
// baseline (speedup 1.0000x reference)
#include <cuda_runtime.h>
#include <cuda_fp16.h>
#include <cstdint>

// W8A16 linear, single-pass fp16 mma.sync (compute_103-safe).
// out[M,N] = (x[M,K] @ W[N,K]^T) * scales[N] + bias[N]
//   Prequant: W int8-in-int32 -> fp16 (exact); x fp32 -> fp16 (rel err 2^-11).
//   GEMM: 1 CTA x 256 thr, tile 128x256, warp tile 64x64, BK=64, 4-stage
//   cp.async + mbarrier pipeline (R11-exact schedule).
//   Wave-tail: tiles 0..1331 = 9 exact waves of 148; last 44 tiles use
//   MIXED split-K totalling exactly 148 CTAs (16 tiles x4 parts + 28 x3),
//   so the grid is exactly 10 waves. Bias folded into part-0 partials;
//   reduce is a vectorized (float4) pure sum.

#define GK 4096
#define GM 4096
#define GN 11008

#define NXT 43                      // N tiles
#define NYT 32                      // M tiles
#define NTILES (NXT * NYT)          // 1376
#define NFULL 1332                  // 9 exact waves x 148
#define NTAIL (NTILES - NFULL)      // 44
#define N4WAY 16                    // first 16 tail tiles: 4 parts (16 chunks)
#define GEMM_GRID (NFULL + 148)     // 1480 = exactly 10 waves

__device__ __half g_xh[(size_t)GM * GK];
__device__ __half g_wh[(size_t)GN * GK];
__device__ float  g_part[(size_t)4 * NTAIL * 128 * 256];   // 23 MB

// ---------------- helpers ----------------
__device__ __forceinline__ uint32_t s2u(const void* p) {
    uint32_t a;
    asm("{ .reg .u64 t; cvta.to.shared.u64 t, %1; cvt.u32.u64 %0, t; }" : "=r"(a) : "l"(p));
    return a;
}
#define CP_ASYNC16(dst, src) \
    asm volatile("cp.async.cg.shared.global [%0], [%1], 16;" :: "r"(dst), "l"(src))

#define LDSM_X4(r0, r1, r2, r3, a)                                              \
    asm volatile("ldmatrix.sync.aligned.m8n8.x4.shared.b16 {%0,%1,%2,%3}, [%4];" \
                 : "=r"(r0), "=r"(r1), "=r"(r2), "=r"(r3) : "r"(a))

#define MBARRIER_INIT(mb, c) \
    asm volatile("mbarrier.init.shared.b64 [%0], %1;" :: "r"((uint32_t)(mb)), "r"((uint32_t)(c)) : "memory")
#define MBARRIER_ARRIVE(mb) \
    asm volatile("mbarrier.arrive.shared.b64 _, [%0];" :: "r"((uint32_t)(mb)) : "memory")
#define CPASYNC_MBAR_ARRIVE(mb) \
    asm volatile("cp.async.mbarrier.arrive.noinc.shared::cta.b64 [%0];" :: "r"((uint32_t)(mb)) : "memory")

#define MBARRIER_WAIT_PARITY(mb, par) do {                                          \
    uint32_t _mb = (uint32_t)(mb); uint32_t _p = (uint32_t)(par); uint32_t _done;   \
    asm volatile("{\n\t.reg .pred p;\n\t"                                           \
        "mbarrier.try_wait.parity.acquire.cta.shared::cta.b64 p, [%1], %2;\n\t"     \
        "selp.b32 %0, 1, 0, p;\n\t}"                                                \
        : "=r"(_done) : "r"(_mb), "r"(_p) : "memory");                              \
    if (!_done) {                                                                   \
        asm volatile("{\n\t.reg .pred P1;\n\t"                                      \
            "WL_%=:\n\t"                                                            \
            "mbarrier.try_wait.parity.acquire.cta.shared::cta.b64 P1, [%0], %1, 0x989680;\n\t" \
            "@P1 bra.uni WD_%=;\n\t"                                                \
            "bra.uni WL_%=;\n\t"                                                    \
            "WD_%=:\n\t}"                                                           \
            :: "r"(_mb), "r"(_p) : "memory");                                       \
    }                                                                               \
} while (0)

// tile index -> (xg, yg) swizzle (SWZ_G = 8)
__device__ __forceinline__ void tile_to_xy(int tile, int& xg, int& yg) {
    const int tps = 8 * NXT;            // 344
    int stripe = tile / tps;
    int rem    = tile - stripe * tps;
    xg = rem >> 3;
    yg = stripe * 8 + (rem & 7);
}

// ---------------- prequant ----------------
__global__ void wprequant_kernel(const int* __restrict__ w, int n4) {
    int stride = gridDim.x * blockDim.x;
    for (int i = blockIdx.x * blockDim.x + threadIdx.x; i < n4; i += stride) {
        int4 v = reinterpret_cast<const int4*>(w)[i];
        __half2 p0 = __floats2half2_rn((float)v.x, (float)v.y);   // exact
        __half2 p1 = __floats2half2_rn((float)v.z, (float)v.w);
        uint2 pk;
        pk.x = *reinterpret_cast<uint32_t*>(&p0);
        pk.y = *reinterpret_cast<uint32_t*>(&p1);
        reinterpret_cast<uint2*>(g_wh)[i] = pk;
    }
}

__global__ void xprequant_kernel(const float* __restrict__ x, int n4) {
    int stride = gridDim.x * blockDim.x;
    for (int i = blockIdx.x * blockDim.x + threadIdx.x; i < n4; i += stride) {
        float4 v = reinterpret_cast<const float4*>(x)[i];
        __half2 p0 = __floats2half2_rn(v.x, v.y);
        __half2 p1 = __floats2half2_rn(v.z, v.w);
        uint2 pk;
        pk.x = *reinterpret_cast<uint32_t*>(&p0);
        pk.y = *reinterpret_cast<uint32_t*>(&p1);
        reinterpret_cast<uint2*>(g_xh)[i] = pk;
    }
}

// ---------------- GEMM ----------------
#define BM 128
#define BN 256
#define BK 64
#define NTHR 256
#define ATILE 16384                 // 128 rows x 128 B
#define BTILE 32768                 // 256 rows x 128 B
#define STAGEB (ATILE + BTILE)      // 49152
#define NSTAGE 4
#define STAGES_B (NSTAGE * STAGEB)  // 196608
#define SMEMB (STAGES_B + 128)      // + mbarriers

__global__ __launch_bounds__(NTHR, 1)
void w8a16_hmma_kernel(const float* __restrict__ scales,
                       const float* __restrict__ bias,
                       float* __restrict__ out,
                       int M, int N, int K)
{
    extern __shared__ char sm[];
    const uint32_t sb = s2u(sm);
    const uint32_t mb_full  = sb + STAGES_B;        // 4 x 8B
    const uint32_t mb_empty = sb + STAGES_B + 32;   // 4 x 8B
    const int tid  = threadIdx.x;
    const int lane = tid & 31;
    const int warp = tid >> 5;
    const int wm = warp >> 2;            // 0..1 -> m offset 64*wm
    const int wn = warp & 3;             // 0..3 -> n offset 64*wn

    // ---- work assignment (mixed split-K tail: exactly 148 CTAs) ----
    const int lb = blockIdx.x;
    int tile, part, kbeg, nch;
    if (lb < NFULL) {
        tile = lb; part = -1; kbeg = 0; nch = K / BK;            // 64
    } else {
        int idx = lb - NFULL;               // 0..147
        int z;
        if (idx < N4WAY * 4) {              // tiles 0..15: 4 parts x 16 chunks
            z    = idx >> 2;
            part = idx & 3;
            kbeg = part * 16;
            nch  = 16;
        } else {                            // tiles 16..43: 3 parts, 22/21/21
            int r = idx - N4WAY * 4;
            z    = N4WAY + r / 3;
            part = r % 3;
            kbeg = (part == 0) ? 0 : (part == 1 ? 22 : 43);
            nch  = (part == 0) ? 22 : 21;
        }
        tile = NFULL + z;
    }
    int xg, yg;
    tile_to_xy(tile, xg, yg);
    const int mbase = yg * BM;
    const int nbase = xg * BN;

    // unified epilogue parameters (bias folded into part-0 partials)
    float*  obase;
    int     ostride;
    float   bmul;
    if (part < 0) {
        obase   = out + (size_t)mbase * N + nbase;
        ostride = N;
        bmul    = 1.0f;
    } else {
        obase   = g_part + ((size_t)part * NTAIL + (tile - NFULL)) * 128 * 256;
        ostride = 256;
        bmul    = (part == 0) ? 1.0f : 0.0f;
    }

    const __half* ag  = g_xh + (size_t)mbase * K;
    const __half* bgp = g_wh + (size_t)nbase * K;

    // ---- mbarrier init ----
    if (tid == 0) {
        #pragma unroll
        for (int s = 0; s < NSTAGE; ++s) {
            MBARRIER_INIT(mb_full  + s * 8, NTHR);
            MBARRIER_INIT(mb_empty + s * 8, 8);
        }
    }
    __syncthreads();

    float acc[4][8][4];
    #pragma unroll
    for (int mi = 0; mi < 4; ++mi)
        #pragma unroll
        for (int ni = 0; ni < 8; ++ni)
            #pragma unroll
            for (int c = 0; c < 4; ++c)
                acc[mi][ni][c] = 0.0f;

    // ldmatrix lane address components (non-trans x4 for both operands)
    const int a_rl = (lane & 7) + ((lane >> 3) & 1) * 8;
    const int a_cb = lane >> 4;
    const int b_rl = (lane & 7) + ((lane >> 4) << 3);
    const int b_cb = (lane >> 3) & 1;

    uint32_t arow[4], am7[4];
    #pragma unroll
    for (int mi = 0; mi < 4; ++mi) {
        int r = wm * 64 + mi * 16 + a_rl;
        arow[mi] = (uint32_t)r * 128;
        am7[mi]  = (uint32_t)(r & 7);
    }
    uint32_t brow[4], bm7[4];
    #pragma unroll
    for (int nj = 0; nj < 4; ++nj) {
        int r = wn * 64 + nj * 16 + b_rl;
        brow[nj] = (uint32_t)r * 128;
        bm7[nj]  = (uint32_t)(r & 7);
    }

    #define ISSUE_STAGE(st, k0) do {                                             \
        uint32_t dstb = sb + (st) * STAGEB;                                      \
        _Pragma("unroll")                                                        \
        for (int cc = 0; cc < 12; ++cc) {                                        \
            int cid  = tid + cc * NTHR;         /* 0..3071 */                    \
            int isB  = cid >= 1024;                                              \
            int rem2 = isB ? (cid - 1024) : cid;                                 \
            int row  = rem2 >> 3;                                                \
            int c    = rem2 & 7;                                                 \
            const __half* src = (isB ? bgp : ag) + (size_t)row * K + (k0) + c * 8; \
            uint32_t dst = dstb + (isB ? ATILE : 0) + row * 128 +                \
                           ((uint32_t)(c ^ (row & 7)) << 4);                     \
            CP_ASYNC16(dst, src);                                                \
        }                                                                        \
        CPASYNC_MBAR_ARRIVE(mb_full + (st) * 8);                                 \
    } while (0)

    // prologue: fill 4 stages with chunks kbeg..kbeg+3
    ISSUE_STAGE(0, kbeg * BK);
    ISSUE_STAGE(1, (kbeg + 1) * BK);
    ISSUE_STAGE(2, (kbeg + 2) * BK);
    ISSUE_STAGE(3, (kbeg + 3) * BK);

    for (int i = 0; i < nch; ++i) {
        const int s = i & 3;
        const int q = (i >> 2) & 1;

        MBARRIER_WAIT_PARITY(mb_full + s * 8, q);

        const uint32_t as = sb + s * STAGEB;
        const uint32_t bs = as + ATILE;

        #pragma unroll
        for (int ks = 0; ks < 4; ++ks) {
            const uint32_t kc2 = (uint32_t)(ks * 2);

            uint32_t bf[4][4];
            #pragma unroll
            for (int nj = 0; nj < 4; ++nj) {
                uint32_t addr = bs + brow[nj] + (((kc2 + b_cb) ^ bm7[nj]) << 4);
                LDSM_X4(bf[nj][0], bf[nj][1], bf[nj][2], bf[nj][3], addr);
            }
            uint32_t af[4][4];
            #pragma unroll
            for (int mi = 0; mi < 4; ++mi) {
                uint32_t addr = as + arow[mi] + (((kc2 + a_cb) ^ am7[mi]) << 4);
                LDSM_X4(af[mi][0], af[mi][1], af[mi][2], af[mi][3], addr);
            }

            #pragma unroll
            for (int mi = 0; mi < 4; ++mi) {
                #pragma unroll
                for (int nj = 0; nj < 4; ++nj) {
                    #pragma unroll
                    for (int h = 0; h < 2; ++h) {
                        const int ni = nj * 2 + h;
                        asm volatile(
                            "mma.sync.aligned.m16n8k16.row.col.f32.f16.f16.f32 "
                            "{%0,%1,%2,%3}, {%4,%5,%6,%7}, {%8,%9}, {%0,%1,%2,%3};\n"
                            : "+f"(acc[mi][ni][0]), "+f"(acc[mi][ni][1]),
                              "+f"(acc[mi][ni][2]), "+f"(acc[mi][ni][3])
                            : "r"(af[mi][0]), "r"(af[mi][1]),
                              "r"(af[mi][2]), "r"(af[mi][3]),
                              "r"(bf[nj][h * 2]), "r"(bf[nj][h * 2 + 1]));
                    }
                }
            }
        }

        if (lane == 0) MBARRIER_ARRIVE(mb_empty + s * 8);

        const int j = i + 4;
        if (j < nch) {
            MBARRIER_WAIT_PARITY(mb_empty + s * 8, q);
            ISSUE_STAGE(s, (kbeg + j) * BK);
        }
    }

    // ---- unified epilogue: y = acc * scales[n] + bias[n]*bmul ----
    #pragma unroll
    for (int mi = 0; mi < 4; ++mi) {
        const int r0 = wm * 64 + mi * 16 + (lane >> 2);
        float* o0 = obase + (size_t)r0 * ostride;
        float* o1 = obase + (size_t)(r0 + 8) * ostride;
        #pragma unroll
        for (int ni = 0; ni < 8; ++ni) {
            const int gn = wn * 64 + ni * 8 + ((lane & 3) << 1);
            const float s0 = scales[nbase + gn], s1 = scales[nbase + gn + 1];
            const float b0 = bias[nbase + gn] * bmul;
            const float b1 = bias[nbase + gn + 1] * bmul;
            float2 v;
            v.x = acc[mi][ni][0] * s0 + b0;
            v.y = acc[mi][ni][1] * s1 + b1;
            *reinterpret_cast<float2*>(o0 + gn) = v;
            v.x = acc[mi][ni][2] * s0 + b0;
            v.y = acc[mi][ni][3] * s1 + b1;
            *reinterpret_cast<float2*>(o1 + gn) = v;
        }
    }
}

// ---------------- tail reduce: out = sum of 3 or 4 partials (bias in p0) ----
__global__ __launch_bounds__(256)
void tailreduce_kernel(float* __restrict__ out, int N) {
    const int z  = blockIdx.x >> 2;        // 0..43
    const int rg = blockIdx.x & 3;         // 32-row group
    const int tid = threadIdx.x;
    int xg, yg;
    tile_to_xy(NFULL + z, xg, yg);
    const int mbase = yg * BM;
    const int nbase = xg * BN;
    const float4* p0 = reinterpret_cast<const float4*>(g_part + ((size_t)0 * NTAIL + z) * 128 * 256);
    const float4* p1 = reinterpret_cast<const float4*>(g_part + ((size_t)1 * NTAIL + z) * 128 * 256);
    const float4* p2 = reinterpret_cast<const float4*>(g_part + ((size_t)2 * NTAIL + z) * 128 * 256);
    const float4* p3 = reinterpret_cast<const float4*>(g_part + ((size_t)3 * NTAIL + z) * 128 * 256);
    const bool has4 = (z < N4WAY);
    #pragma unroll
    for (int it = 0; it < 8; ++it) {
        const int fi   = rg * 2048 + it * 256 + tid;   // float4 idx in 128x64 grid
        const int row  = fi >> 6;
        const int col4 = fi & 63;
        float4 a = p0[fi], b = p1[fi], c = p2[fi];
        float4 v;
        v.x = (a.x + b.x) + c.x;
        v.y = (a.y + b.y) + c.y;
        v.z = (a.z + b.z) + c.z;
        v.w = (a.w + b.w) + c.w;
        if (has4) {
            float4 d = p3[fi];
            v.x += d.x; v.y += d.y; v.z += d.z; v.w += d.w;
        }
        *reinterpret_cast<float4*>(out + (size_t)(mbase + row) * N + nbase + col4 * 4) = v;
    }
}

extern "C" void kernel_launch(void* const* d_in, const int* in_sizes, int n_in,
                              void* d_out, int out_size)
{
    const float* x      = (const float*) d_in[0];
    const int*   w      = (const int*)   d_in[1];   // int8 values in int32 storage
    const float* scales = (const float*) d_in[2];
    const float* bias   = (const float*) d_in[3];
    float*       out    = (float*)       d_out;

    const int N = in_sizes[2];            // 11008
    const int K = in_sizes[1] / N;        // 4096
    const int M = in_sizes[0] / K;        // 4096

    cudaFuncSetAttribute(w8a16_hmma_kernel,
                         cudaFuncAttributeMaxDynamicSharedMemorySize, SMEMB);

    wprequant_kernel<<<2048, 256>>>(w, (N * K) / 4);
    xprequant_kernel<<<2048, 256>>>(x, (M * K) / 4);
    w8a16_hmma_kernel<<<GEMM_GRID, NTHR, SMEMB>>>(scales, bias, out, M, N, K);
    tailreduce_kernel<<<NTAIL * 4, 256>>>(out, N);
}